// round 1
// baseline (speedup 1.0000x reference)
#include <cuda_runtime.h>
#include <math.h>

// Problem constants
#define NN   50000
#define EE   300000
#define FEA  64
#define HD   256
#define GG   256
#define LL   4
#define OUTD 128
#define LH   (LL*HD)   // 1024

// ---------------- scratch (device globals; no allocation allowed) ----------
__device__ float g_tmp [(size_t)EE*HD];   // bond layer1 out
__device__ float g_e   [(size_t)EE*HD];   // bond layer2 out (edge embedding)
__device__ float g_aggr[(size_t)NN*HD];
__device__ float g_t2  [(size_t)NN*HD];
__device__ float g_h   [(size_t)NN*HD];
__device__ float g_xc  [(size_t)NN*LH];   // concat of per-layer outputs
__device__ float g_sum [HD];
__device__ float g_ssq [HD];
__device__ float g_pooled[GG*LH];
__device__ float g_hh  [GG*HD];
__device__ int   g_src [EE];
__device__ int   g_dst [EE];
__device__ int   g_batch[NN];
__device__ int   g_off [GG+1];

// ---------------- index conversion (handles int64 or int32 inputs) ---------
__global__ void cvt_kernel(const int* __restrict__ ei_raw,
                           const int* __restrict__ batch_raw) {
    // If the buffer is int64 (little-endian, values < 2^31, non-negative),
    // the odd 32-bit words are zero. Probe three of them.
    bool is64 = (ei_raw[1] == 0) && (ei_raw[3] == 0) && (ei_raw[5] == 0);
    int idx = blockIdx.x * blockDim.x + threadIdx.x;
    int stride = gridDim.x * blockDim.x;
    for (int i = idx; i < EE; i += stride) {
        g_src[i] = is64 ? ei_raw[2*i]          : ei_raw[i];
        g_dst[i] = is64 ? ei_raw[2*(EE + i)]   : ei_raw[EE + i];
    }
    for (int i = idx; i < NN; i += stride) {
        g_batch[i] = is64 ? batch_raw[2*i] : batch_raw[i];
    }
}

// ---------------- segment offsets via binary search (batch is sorted) ------
__global__ void off_kernel() {
    int g = blockIdx.x * blockDim.x + threadIdx.x;
    if (g > GG) return;
    int lo = 0, hi = NN;
    while (lo < hi) {
        int mid = (lo + hi) >> 1;
        if (g_batch[mid] < g) lo = mid + 1; else hi = mid;
    }
    g_off[g] = lo;
}

// ---------------- tiled SGEMM: C = A[M,K] * B[K,N] + bias (optional ReLU) --
// Requirements: K % BK == 0, N % BN == 0, lda/ldb/ldc % 4 == 0. M guarded.
template<int BM, int BN, int BK, int TM, int TN, bool RELU>
__global__ void sgemm_bias(int M, int Nc, int K,
                           const float* __restrict__ A, int lda,
                           const float* __restrict__ B, int ldb,
                           const float* __restrict__ bias,
                           float* __restrict__ C, int ldc) {
    __shared__ float As[BK * BM];
    __shared__ float Bs[BK * BN];

    const int tid = threadIdx.x;              // 256 threads
    const int cRow = blockIdx.y;
    const int cCol = blockIdx.x;

    const int threadCol = tid % (BN / TN);    // 0..15
    const int threadRow = tid / (BN / TN);    // 0..15

    const int innerRowA = tid / (BK / 4);     // 0..127
    const int innerColA = (tid % (BK / 4)) * 4;
    const int innerRowB = tid / (BN / 4);     // 0..7
    const int innerColB = (tid % (BN / 4)) * 4;

    const int globalRowBase = cRow * BM;
    const float* Ap = A + (size_t)globalRowBase * lda;
    const float* Bp = B + cCol * BN;
    float* Cp = C + (size_t)globalRowBase * ldc + cCol * BN;

    float acc[TM * TN];
    #pragma unroll
    for (int i = 0; i < TM * TN; i++) acc[i] = 0.0f;
    float regM[TM], regN[TN];

    for (int k0 = 0; k0 < K; k0 += BK) {
        // load A tile (BM x BK), transposed into As[k][m]
        {
            float4 v = make_float4(0.f, 0.f, 0.f, 0.f);
            if (globalRowBase + innerRowA < M)
                v = *reinterpret_cast<const float4*>(Ap + (size_t)innerRowA * lda + innerColA);
            As[(innerColA + 0) * BM + innerRowA] = v.x;
            As[(innerColA + 1) * BM + innerRowA] = v.y;
            As[(innerColA + 2) * BM + innerRowA] = v.z;
            As[(innerColA + 3) * BM + innerRowA] = v.w;
        }
        // load B tile (BK x BN)
        {
            float4 v = *reinterpret_cast<const float4*>(Bp + (size_t)innerRowB * ldb + innerColB);
            *reinterpret_cast<float4*>(&Bs[innerRowB * BN + innerColB]) = v;
        }
        __syncthreads();
        Ap += BK;
        Bp += (size_t)BK * ldb;

        #pragma unroll
        for (int k = 0; k < BK; k++) {
            #pragma unroll
            for (int i = 0; i < TM; i++) regM[i] = As[k * BM + threadRow * TM + i];
            #pragma unroll
            for (int j = 0; j < TN; j++) regN[j] = Bs[k * BN + threadCol * TN + j];
            #pragma unroll
            for (int i = 0; i < TM; i++)
                #pragma unroll
                for (int j = 0; j < TN; j++)
                    acc[i * TN + j] += regM[i] * regN[j];
        }
        __syncthreads();
    }

    // epilogue: bias (+ReLU), float4 stores, row-guarded
    #pragma unroll
    for (int i = 0; i < TM; i++) {
        int row = threadRow * TM + i;
        if (globalRowBase + row >= M) continue;
        #pragma unroll
        for (int j = 0; j < TN; j += 4) {
            int col = threadCol * TN + j;
            float4 v;
            v.x = acc[i * TN + j + 0] + bias[cCol * BN + col + 0];
            v.y = acc[i * TN + j + 1] + bias[cCol * BN + col + 1];
            v.z = acc[i * TN + j + 2] + bias[cCol * BN + col + 2];
            v.w = acc[i * TN + j + 3] + bias[cCol * BN + col + 3];
            if (RELU) {
                v.x = fmaxf(v.x, 0.f); v.y = fmaxf(v.y, 0.f);
                v.z = fmaxf(v.z, 0.f); v.w = fmaxf(v.w, 0.f);
            }
            *reinterpret_cast<float4*>(Cp + (size_t)row * ldc + col) = v;
        }
    }
}

// ---------------- aggr = (1+eps[l]) * x_in -------------------------------
__global__ void init_aggr_k(const float* __restrict__ xin, int ldx,
                            const float* __restrict__ eps, int l) {
    float a = 1.0f + eps[l];
    int i = blockIdx.x * blockDim.x + threadIdx.x;
    const int total = NN * (HD / 4);
    if (i < total) {
        int row = i / (HD / 4);
        int c4  = i % (HD / 4);
        float4 v = *reinterpret_cast<const float4*>(xin + (size_t)row * ldx + c4 * 4);
        float4 o = make_float4(a * v.x, a * v.y, a * v.z, a * v.w);
        *reinterpret_cast<float4*>(g_aggr + (size_t)row * HD + c4 * 4) = o;
    }
}

// ---------------- aggr[dst] += relu(x[src] + e) --------------------------
__global__ void scatter_k(const float* __restrict__ xin, int ldx) {
    int gwarp = (blockIdx.x * blockDim.x + threadIdx.x) >> 5;
    int lane  = threadIdx.x & 31;
    int nw    = (gridDim.x * blockDim.x) >> 5;
    for (int eidx = gwarp; eidx < EE; eidx += nw) {
        int s = g_src[eidx];
        int d = g_dst[eidx];
        const float4* ep = reinterpret_cast<const float4*>(g_e + (size_t)eidx * HD);
        const float4* xp = reinterpret_cast<const float4*>(xin + (size_t)s * ldx);
        float* ag = g_aggr + (size_t)d * HD;
        #pragma unroll
        for (int i = 0; i < 2; i++) {
            int c4 = lane + i * 32;   // 0..63
            float4 ev = ep[c4];
            float4 xv = xp[c4];
            float4 m = make_float4(fmaxf(ev.x + xv.x, 0.f), fmaxf(ev.y + xv.y, 0.f),
                                   fmaxf(ev.z + xv.z, 0.f), fmaxf(ev.w + xv.w, 0.f));
            atomicAdd(ag + c4 * 4 + 0, m.x);
            atomicAdd(ag + c4 * 4 + 1, m.y);
            atomicAdd(ag + c4 * 4 + 2, m.z);
            atomicAdd(ag + c4 * 4 + 3, m.w);
        }
    }
}

// ---------------- batchnorm: column stats + apply -------------------------
__global__ void zero_stats_k() {
    int t = threadIdx.x;
    if (t < HD) { g_sum[t] = 0.f; g_ssq[t] = 0.f; }
}

__global__ void bn_reduce_k() {
    int col = threadIdx.x;                 // 256 threads, one column each
    float s = 0.f, ss = 0.f;
    for (int r = blockIdx.x; r < NN; r += gridDim.x) {
        float v = g_h[(size_t)r * HD + col];
        s += v; ss += v * v;
    }
    atomicAdd(&g_sum[col], s);
    atomicAdd(&g_ssq[col], ss);
}

__global__ void bn_apply_k(const float* __restrict__ gamma,
                           const float* __restrict__ beta, int l) {
    int i = blockIdx.x * blockDim.x + threadIdx.x;
    if (i >= NN * HD) return;
    int col = i & (HD - 1);
    int row = i >> 8;
    float mu  = g_sum[col] * (1.0f / NN);
    float var = g_ssq[col] * (1.0f / NN) - mu * mu;
    float sc  = gamma[col] * rsqrtf(var + 1e-5f);
    g_xc[(size_t)row * LH + l * HD + col] = (g_h[i] - mu) * sc + beta[col];
}

// ---------------- global mean pool (per-graph, atomic-free) ---------------
__global__ void pool_k() {
    int g   = blockIdx.y;
    int col = blockIdx.x * blockDim.x + threadIdx.x;  // 0..1023
    int s  = g_off[g];
    int e2 = g_off[g + 1];
    float acc = 0.f;
    for (int r = s; r < e2; r++) acc += g_xc[(size_t)r * LH + col];
    float cnt = (float)(e2 - s);
    g_pooled[g * LH + col] = acc / fmaxf(cnt, 1.0f);
}

// ---------------- host launcher -------------------------------------------
extern "C" void kernel_launch(void* const* d_in, const int* in_sizes, int n_in,
                              void* d_out, int out_size) {
    const float* x         = (const float*)d_in[0];
    const int*   ei_raw    = (const int*)  d_in[1];
    const float* edge_attr = (const float*)d_in[2];
    const int*   batch_raw = (const int*)  d_in[3];
    const float* bond_W1   = (const float*)d_in[4];
    const float* bond_b1   = (const float*)d_in[5];
    const float* bond_W2   = (const float*)d_in[6];
    const float* bond_b2   = (const float*)d_in[7];
    const float* mlp_W1    = (const float*)d_in[8];
    const float* mlp_b1    = (const float*)d_in[9];
    const float* mlp_W2    = (const float*)d_in[10];
    const float* mlp_b2    = (const float*)d_in[11];
    const float* eps       = (const float*)d_in[12];
    const float* bn_gamma  = (const float*)d_in[13];
    const float* bn_beta   = (const float*)d_in[14];
    const float* fc1_W     = (const float*)d_in[15];
    const float* fc1_b     = (const float*)d_in[16];
    const float* fc4_W     = (const float*)d_in[17];
    const float* fc4_b     = (const float*)d_in[18];
    float* out = (float*)d_out;

    float *tmp, *e, *aggr, *t2, *h, *xc, *pooled, *hh;
    cudaGetSymbolAddress((void**)&tmp,    g_tmp);
    cudaGetSymbolAddress((void**)&e,      g_e);
    cudaGetSymbolAddress((void**)&aggr,   g_aggr);
    cudaGetSymbolAddress((void**)&t2,     g_t2);
    cudaGetSymbolAddress((void**)&h,      g_h);
    cudaGetSymbolAddress((void**)&xc,     g_xc);
    cudaGetSymbolAddress((void**)&pooled, g_pooled);
    cudaGetSymbolAddress((void**)&hh,     g_hh);

    cvt_kernel<<<256, 256>>>(ei_raw, batch_raw);
    off_kernel<<<2, 256>>>();

    const int rowsE = (EE + 127) / 128;
    const int rowsN = (NN + 127) / 128;

    const float* xin = x;
    int ldx = HD;

    for (int l = 0; l < LL; l++) {
        // bond encoder: tmp = relu(edge_attr @ W1 + b1); e = tmp @ W2 + b2
        sgemm_bias<128,128,8,8,8,true ><<<dim3(HD/128, rowsE), 256>>>(
            EE, HD, FEA, edge_attr, FEA,
            bond_W1 + (size_t)l*FEA*HD, HD, bond_b1 + l*HD, tmp, HD);
        sgemm_bias<128,128,8,8,8,false><<<dim3(HD/128, rowsE), 256>>>(
            EE, HD, HD, tmp, HD,
            bond_W2 + (size_t)l*HD*HD, HD, bond_b2 + l*HD, e, HD);

        // aggregate: aggr = (1+eps)x + scatter_add(relu(x[src]+e))
        init_aggr_k<<<(NN*(HD/4) + 255)/256, 256>>>(xin, ldx, eps, l);
        scatter_k<<<2048, 256>>>(xin, ldx);

        // node MLP: t2 = relu(aggr@W1+b1); h = relu(t2@W2+b2)
        sgemm_bias<128,128,8,8,8,true ><<<dim3(HD/128, rowsN), 256>>>(
            NN, HD, HD, aggr, HD,
            mlp_W1 + (size_t)l*HD*HD, HD, mlp_b1 + l*HD, t2, HD);
        sgemm_bias<128,128,8,8,8,true ><<<dim3(HD/128, rowsN), 256>>>(
            NN, HD, HD, t2, HD,
            mlp_W2 + (size_t)l*HD*HD, HD, mlp_b2 + l*HD, h, HD);

        // batchnorm -> write into concat slice
        zero_stats_k<<<1, 256>>>();
        bn_reduce_k<<<512, 256>>>();
        bn_apply_k<<<(NN*HD + 255)/256, 256>>>(bn_gamma + l*HD, bn_beta + l*HD, l);

        xin = xc + l*HD;
        ldx = LH;
    }

    // pooled[G, LH] = per-graph mean of xc
    pool_k<<<dim3(LH/256, GG), 256>>>();

    // fc1 (relu) then fc4
    sgemm_bias<128,128,8,8,8,true ><<<dim3(HD/128, (GG+127)/128), 256>>>(
        GG, HD, LH, pooled, LH, fc1_W, HD, fc1_b, hh, HD);
    sgemm_bias<128,128,8,8,8,false><<<dim3(OUTD/128, (GG+127)/128), 256>>>(
        GG, OUTD, HD, hh, HD, fc4_W, OUTD, fc4_b, out, OUTD);
}

// round 4
// speedup vs baseline: 1.1811x; 1.1811x over previous
#include <cuda_runtime.h>
#include <cstdint>
#include <math.h>

#define NN   50000
#define EE   300000
#define FEA  64
#define HD   256
#define GG   256
#define LL   4
#define OUTD 128
#define LH   (LL*HD)   // 1024

// ---------------- scratch (device globals) ---------------------------------
__device__ float g_tmp [(size_t)EE*HD];
__device__ float g_e   [(size_t)EE*HD];
__device__ float g_aggr[(size_t)NN*HD];
__device__ float g_t2  [(size_t)NN*HD];
__device__ float g_h   [(size_t)NN*HD];
__device__ float g_xc  [(size_t)NN*LH];
__device__ float g_sum [HD];
__device__ float g_ssq [HD];
__device__ float g_pooled[GG*LH];
__device__ float g_hh  [GG*HD];
__device__ int   g_src [EE];
__device__ int   g_dst [EE];
__device__ int   g_batch[NN];
__device__ int   g_off [GG+1];
// transposed weights, tf32 hi/lo split: layout [Ntot, K] row-major
__device__ float g_bW1h[LL*HD*FEA], g_bW1l[LL*HD*FEA];
__device__ float g_bW2h[LL*HD*HD],  g_bW2l[LL*HD*HD];
__device__ float g_mW1h[LL*HD*HD],  g_mW1l[LL*HD*HD];
__device__ float g_mW2h[LL*HD*HD],  g_mW2l[LL*HD*HD];
__device__ float g_f1h [HD*LH],     g_f1l [HD*LH];
__device__ float g_f4h [OUTD*HD],   g_f4l [OUTD*HD];

// ---------------- helpers ---------------------------------------------------
__device__ __forceinline__ float to_tf32(float v) {
    float r;
    asm("cvt.rna.tf32.f32 %0, %1;" : "=f"(r) : "f"(v));
    return r;
}
__device__ __forceinline__ void mma_tf32(float* d, const uint32_t* a,
                                         uint32_t b0, uint32_t b1) {
    asm volatile(
        "mma.sync.aligned.m16n8k8.row.col.f32.tf32.tf32.f32 "
        "{%0,%1,%2,%3}, {%4,%5,%6,%7}, {%8,%9}, {%0,%1,%2,%3};"
        : "+f"(d[0]), "+f"(d[1]), "+f"(d[2]), "+f"(d[3])
        : "r"(a[0]), "r"(a[1]), "r"(a[2]), "r"(a[3]), "r"(b0), "r"(b1));
}

// SMEM geometry (floats): A hi/lo [32 k][132], B hi/lo [128 n][36]
#define SA 132
#define SB 36
#define SMEM_A_ELEMS (32*SA)
#define SMEM_B_ELEMS (128*SB)
#define TC_SMEM_BYTES ((2*SMEM_A_ELEMS + 2*SMEM_B_ELEMS) * 4)   // 70656

// ---------------- tensor-core 3xTF32 GEMM: C = A[M,K] @ B + bias -----------
// B pre-transposed as Bhi/Blo [Ntot, K] row-major.  K % 32 == 0, Ntot % 128 == 0.
template<bool RELU>
__global__ void __launch_bounds__(256, 2)
tc_gemm(int M, int K,
        const float* __restrict__ A, int lda,
        const float* __restrict__ Bhi, const float* __restrict__ Blo,
        const float* __restrict__ bias,
        float* __restrict__ C, int ldc)
{
    extern __shared__ float smf[];
    float* Ahs = smf;
    float* Als = Ahs + SMEM_A_ELEMS;
    float* Bhs = Als + SMEM_A_ELEMS;
    float* Bls = Bhs + SMEM_B_ELEMS;

    const int tid  = threadIdx.x;
    const int wid  = tid >> 5;
    const int lane = tid & 31;
    const int warp_m = wid & 1;     // 2 warps over M (64 each)
    const int warp_n = wid >> 1;    // 4 warps over N (32 each)
    const int m0 = blockIdx.y * 128;
    const int n0 = blockIdx.x * 128;

    const int ldrow  = tid >> 1;    // 0..127
    const int ldhalf = tid & 1;     // which 16-wide k half
    const bool aok = (m0 + ldrow) < M;

    float acc[4][4][4];
    #pragma unroll
    for (int i = 0; i < 4; i++)
        #pragma unroll
        for (int j = 0; j < 4; j++)
            #pragma unroll
            for (int q = 0; q < 4; q++) acc[i][j][q] = 0.f;

    const int grp = lane >> 2;      // 0..7
    const int qid = lane & 3;       // 0..3

    const int nch = K >> 5;
    for (int c = 0; c < nch; c++) {
        __syncthreads();   // previous iteration's fragment LDS complete
        // ---- stage A hi/lo (cvt to tf32) and B hi/lo tiles ----
        {
            const int kbase = c * 32 + ldhalf * 16;
            const float* Ap = A   + (size_t)(m0 + ldrow) * lda + kbase;
            const float* Bh = Bhi + (size_t)(n0 + ldrow) * K   + kbase;
            const float* Bl = Blo + (size_t)(n0 + ldrow) * K   + kbase;
            #pragma unroll
            for (int j = 0; j < 4; j++) {
                const int k = ldhalf * 16 + j * 4;
                float4 av = aok ? *(const float4*)(Ap + j * 4)
                                : make_float4(0.f, 0.f, 0.f, 0.f);
                float h0 = to_tf32(av.x), h1 = to_tf32(av.y);
                float h2 = to_tf32(av.z), h3 = to_tf32(av.w);
                Ahs[(k + 0) * SA + ldrow] = h0;
                Ahs[(k + 1) * SA + ldrow] = h1;
                Ahs[(k + 2) * SA + ldrow] = h2;
                Ahs[(k + 3) * SA + ldrow] = h3;
                Als[(k + 0) * SA + ldrow] = to_tf32(av.x - h0);
                Als[(k + 1) * SA + ldrow] = to_tf32(av.y - h1);
                Als[(k + 2) * SA + ldrow] = to_tf32(av.z - h2);
                Als[(k + 3) * SA + ldrow] = to_tf32(av.w - h3);
                float4 bh = *(const float4*)(Bh + j * 4);
                float4 bl = *(const float4*)(Bl + j * 4);
                Bhs[ldrow * SB + k + 0] = bh.x;
                Bhs[ldrow * SB + k + 1] = bh.y;
                Bhs[ldrow * SB + k + 2] = bh.z;
                Bhs[ldrow * SB + k + 3] = bh.w;
                Bls[ldrow * SB + k + 0] = bl.x;
                Bls[ldrow * SB + k + 1] = bl.y;
                Bls[ldrow * SB + k + 2] = bl.z;
                Bls[ldrow * SB + k + 3] = bl.w;
            }
        }
        __syncthreads();

        const uint32_t* Ahu = (const uint32_t*)Ahs;
        const uint32_t* Alu = (const uint32_t*)Als;
        const uint32_t* Bhu = (const uint32_t*)Bhs;
        const uint32_t* Blu = (const uint32_t*)Bls;

        #pragma unroll
        for (int ks = 0; ks < 4; ks++) {
            const int kk = ks * 8 + qid;
            uint32_t afh[4][4], afl[4][4];
            #pragma unroll
            for (int mf = 0; mf < 4; mf++) {
                const int mr = warp_m * 64 + mf * 16 + grp;
                afh[mf][0] = Ahu[(kk    ) * SA + mr    ];
                afh[mf][1] = Ahu[(kk    ) * SA + mr + 8];
                afh[mf][2] = Ahu[(kk + 4) * SA + mr    ];
                afh[mf][3] = Ahu[(kk + 4) * SA + mr + 8];
                afl[mf][0] = Alu[(kk    ) * SA + mr    ];
                afl[mf][1] = Alu[(kk    ) * SA + mr + 8];
                afl[mf][2] = Alu[(kk + 4) * SA + mr    ];
                afl[mf][3] = Alu[(kk + 4) * SA + mr + 8];
            }
            #pragma unroll
            for (int nf = 0; nf < 4; nf++) {
                const int nn = warp_n * 32 + nf * 8 + grp;
                uint32_t bh0 = Bhu[nn * SB + kk];
                uint32_t bh1 = Bhu[nn * SB + kk + 4];
                uint32_t bl0 = Blu[nn * SB + kk];
                uint32_t bl1 = Blu[nn * SB + kk + 4];
                #pragma unroll
                for (int mf = 0; mf < 4; mf++) {
                    mma_tf32(acc[mf][nf], afh[mf], bh0, bh1);  // Ah*Bh
                    mma_tf32(acc[mf][nf], afh[mf], bl0, bl1);  // Ah*Bl
                    mma_tf32(acc[mf][nf], afl[mf], bh0, bh1);  // Al*Bh
                }
            }
        }
    }

    // ---- epilogue: bias (+ReLU), float2 stores ----
    #pragma unroll
    for (int mf = 0; mf < 4; mf++) {
        #pragma unroll
        for (int half = 0; half < 2; half++) {
            const int row = m0 + warp_m * 64 + mf * 16 + grp + half * 8;
            if (row >= M) continue;
            #pragma unroll
            for (int nf = 0; nf < 4; nf++) {
                const int col = n0 + warp_n * 32 + nf * 8 + 2 * qid;
                float v0 = acc[mf][nf][2 * half + 0] + bias[col];
                float v1 = acc[mf][nf][2 * half + 1] + bias[col + 1];
                if (RELU) { v0 = fmaxf(v0, 0.f); v1 = fmaxf(v1, 0.f); }
                *(float2*)(C + (size_t)row * ldc + col) = make_float2(v0, v1);
            }
        }
    }
}

// ---------------- weight transpose + tf32 hi/lo split ----------------------
// in: [Lc, K, N]  ->  hi/lo: [Lc, N, K]
__global__ void transpose_hilo_k(const float* __restrict__ in,
                                 float* __restrict__ hi, float* __restrict__ lo,
                                 int Lc, int K, int N) {
    int i = blockIdx.x * blockDim.x + threadIdx.x;
    int tot = Lc * K * N;
    if (i >= tot) return;
    int l = i / (K * N);
    int r = i % (K * N);
    int k = r / N, n = r % N;
    float v = in[i];
    float h = to_tf32(v);
    size_t o = (size_t)l * K * N + (size_t)n * K + k;
    hi[o] = h;
    lo[o] = to_tf32(v - h);
}

// ---------------- index conversion (int64 or int32) ------------------------
__global__ void cvt_kernel(const int* __restrict__ ei_raw,
                           const int* __restrict__ batch_raw) {
    bool is64 = (ei_raw[1] == 0) && (ei_raw[3] == 0) && (ei_raw[5] == 0);
    int idx = blockIdx.x * blockDim.x + threadIdx.x;
    int stride = gridDim.x * blockDim.x;
    for (int i = idx; i < EE; i += stride) {
        g_src[i] = is64 ? ei_raw[2*i]        : ei_raw[i];
        g_dst[i] = is64 ? ei_raw[2*(EE + i)] : ei_raw[EE + i];
    }
    for (int i = idx; i < NN; i += stride)
        g_batch[i] = is64 ? batch_raw[2*i] : batch_raw[i];
}

__global__ void off_kernel() {
    int g = blockIdx.x * blockDim.x + threadIdx.x;
    if (g > GG) return;
    int lo = 0, hi = NN;
    while (lo < hi) {
        int mid = (lo + hi) >> 1;
        if (g_batch[mid] < g) lo = mid + 1; else hi = mid;
    }
    g_off[g] = lo;
}

// ---------------- aggr = (1+eps[l]) * x_in ---------------------------------
__global__ void init_aggr_k(const float* __restrict__ xin, int ldx,
                            const float* __restrict__ eps, int l) {
    float a = 1.0f + eps[l];
    int i = blockIdx.x * blockDim.x + threadIdx.x;
    const int total = NN * (HD / 4);
    if (i < total) {
        int row = i / (HD / 4);
        int c4  = i % (HD / 4);
        float4 v = *reinterpret_cast<const float4*>(xin + (size_t)row * ldx + c4 * 4);
        float4 o = make_float4(a*v.x, a*v.y, a*v.z, a*v.w);
        *reinterpret_cast<float4*>(g_aggr + (size_t)row * HD + c4 * 4) = o;
    }
}

// ---------------- aggr[dst] += relu(x[src] + e) ----------------------------
__global__ void scatter_k(const float* __restrict__ xin, int ldx) {
    int gwarp = (blockIdx.x * blockDim.x + threadIdx.x) >> 5;
    int lane  = threadIdx.x & 31;
    int nw    = (gridDim.x * blockDim.x) >> 5;
    for (int eidx = gwarp; eidx < EE; eidx += nw) {
        int s = g_src[eidx];
        int d = g_dst[eidx];
        const float4* ep = reinterpret_cast<const float4*>(g_e + (size_t)eidx * HD);
        const float4* xp = reinterpret_cast<const float4*>(xin + (size_t)s * ldx);
        float* ag = g_aggr + (size_t)d * HD;
        #pragma unroll
        for (int i = 0; i < 2; i++) {
            int c4 = lane + i * 32;
            float4 ev = ep[c4];
            float4 xv = xp[c4];
            float4 m = make_float4(fmaxf(ev.x + xv.x, 0.f), fmaxf(ev.y + xv.y, 0.f),
                                   fmaxf(ev.z + xv.z, 0.f), fmaxf(ev.w + xv.w, 0.f));
            atomicAdd(ag + c4 * 4 + 0, m.x);
            atomicAdd(ag + c4 * 4 + 1, m.y);
            atomicAdd(ag + c4 * 4 + 2, m.z);
            atomicAdd(ag + c4 * 4 + 3, m.w);
        }
    }
}

// ---------------- batchnorm -------------------------------------------------
__global__ void zero_stats_k() {
    int t = threadIdx.x;
    if (t < HD) { g_sum[t] = 0.f; g_ssq[t] = 0.f; }
}
__global__ void bn_reduce_k() {
    int col = threadIdx.x;
    float s = 0.f, ss = 0.f;
    for (int r = blockIdx.x; r < NN; r += gridDim.x) {
        float v = g_h[(size_t)r * HD + col];
        s += v; ss += v * v;
    }
    atomicAdd(&g_sum[col], s);
    atomicAdd(&g_ssq[col], ss);
}
__global__ void bn_apply_k(const float* __restrict__ gamma,
                           const float* __restrict__ beta, int l) {
    int i = blockIdx.x * blockDim.x + threadIdx.x;
    if (i >= NN * HD) return;
    int col = i & (HD - 1);
    int row = i >> 8;
    float mu  = g_sum[col] * (1.0f / NN);
    float var = g_ssq[col] * (1.0f / NN) - mu * mu;
    float sc  = gamma[col] * rsqrtf(var + 1e-5f);
    g_xc[(size_t)row * LH + l * HD + col] = (g_h[i] - mu) * sc + beta[col];
}

// ---------------- global mean pool ------------------------------------------
__global__ void pool_k() {
    int g   = blockIdx.y;
    int col = blockIdx.x * blockDim.x + threadIdx.x;
    int s  = g_off[g];
    int e2 = g_off[g + 1];
    float acc = 0.f;
    for (int r = s; r < e2; r++) acc += g_xc[(size_t)r * LH + col];
    float cnt = (float)(e2 - s);
    g_pooled[g * LH + col] = acc / fmaxf(cnt, 1.0f);
}

// ---------------- host-side GEMM launcher -----------------------------------
static void launch_gemm(bool relu, int M, int K, int Ntot,
                        const float* A, int lda,
                        const float* Bh, const float* Bl,
                        const float* bias, float* C, int ldc) {
    dim3 grid(Ntot / 128, (M + 127) / 128);
    if (relu) {
        cudaFuncSetAttribute(tc_gemm<true>,
            cudaFuncAttributeMaxDynamicSharedMemorySize, TC_SMEM_BYTES);
        tc_gemm<true><<<grid, 256, TC_SMEM_BYTES>>>(M, K, A, lda, Bh, Bl, bias, C, ldc);
    } else {
        cudaFuncSetAttribute(tc_gemm<false>,
            cudaFuncAttributeMaxDynamicSharedMemorySize, TC_SMEM_BYTES);
        tc_gemm<false><<<grid, 256, TC_SMEM_BYTES>>>(M, K, A, lda, Bh, Bl, bias, C, ldc);
    }
}

// ---------------- entry ------------------------------------------------------
extern "C" void kernel_launch(void* const* d_in, const int* in_sizes, int n_in,
                              void* d_out, int out_size) {
    const float* x         = (const float*)d_in[0];
    const int*   ei_raw    = (const int*)  d_in[1];
    const float* edge_attr = (const float*)d_in[2];
    const int*   batch_raw = (const int*)  d_in[3];
    const float* bond_W1   = (const float*)d_in[4];
    const float* bond_b1   = (const float*)d_in[5];
    const float* bond_W2   = (const float*)d_in[6];
    const float* bond_b2   = (const float*)d_in[7];
    const float* mlp_W1    = (const float*)d_in[8];
    const float* mlp_b1    = (const float*)d_in[9];
    const float* mlp_W2    = (const float*)d_in[10];
    const float* mlp_b2    = (const float*)d_in[11];
    const float* eps       = (const float*)d_in[12];
    const float* bn_gamma  = (const float*)d_in[13];
    const float* bn_beta   = (const float*)d_in[14];
    const float* fc1_W     = (const float*)d_in[15];
    const float* fc1_b     = (const float*)d_in[16];
    const float* fc4_W     = (const float*)d_in[17];
    const float* fc4_b     = (const float*)d_in[18];
    float* out = (float*)d_out;

    float *tmp, *e, *aggr, *t2, *h, *xc, *pooled, *hh;
    cudaGetSymbolAddress((void**)&tmp,    g_tmp);
    cudaGetSymbolAddress((void**)&e,      g_e);
    cudaGetSymbolAddress((void**)&aggr,   g_aggr);
    cudaGetSymbolAddress((void**)&t2,     g_t2);
    cudaGetSymbolAddress((void**)&h,      g_h);
    cudaGetSymbolAddress((void**)&xc,     g_xc);
    cudaGetSymbolAddress((void**)&pooled, g_pooled);
    cudaGetSymbolAddress((void**)&hh,     g_hh);
    float *bW1h,*bW1l,*bW2h,*bW2l,*mW1h,*mW1l,*mW2h,*mW2l,*f1h,*f1l,*f4h,*f4l;
    cudaGetSymbolAddress((void**)&bW1h, g_bW1h); cudaGetSymbolAddress((void**)&bW1l, g_bW1l);
    cudaGetSymbolAddress((void**)&bW2h, g_bW2h); cudaGetSymbolAddress((void**)&bW2l, g_bW2l);
    cudaGetSymbolAddress((void**)&mW1h, g_mW1h); cudaGetSymbolAddress((void**)&mW1l, g_mW1l);
    cudaGetSymbolAddress((void**)&mW2h, g_mW2h); cudaGetSymbolAddress((void**)&mW2l, g_mW2l);
    cudaGetSymbolAddress((void**)&f1h,  g_f1h);  cudaGetSymbolAddress((void**)&f1l,  g_f1l);
    cudaGetSymbolAddress((void**)&f4h,  g_f4h);  cudaGetSymbolAddress((void**)&f4l,  g_f4l);

    cvt_kernel<<<256, 256>>>(ei_raw, batch_raw);
    off_kernel<<<2, 256>>>();

    // transpose + hi/lo split all weights
    transpose_hilo_k<<<(LL*FEA*HD + 255)/256, 256>>>(bond_W1, bW1h, bW1l, LL, FEA, HD);
    transpose_hilo_k<<<(LL*HD*HD  + 255)/256, 256>>>(bond_W2, bW2h, bW2l, LL, HD,  HD);
    transpose_hilo_k<<<(LL*HD*HD  + 255)/256, 256>>>(mlp_W1,  mW1h, mW1l, LL, HD,  HD);
    transpose_hilo_k<<<(LL*HD*HD  + 255)/256, 256>>>(mlp_W2,  mW2h, mW2l, LL, HD,  HD);
    transpose_hilo_k<<<(LH*HD     + 255)/256, 256>>>(fc1_W,   f1h,  f1l,  1,  LH,  HD);
    transpose_hilo_k<<<(HD*OUTD   + 255)/256, 256>>>(fc4_W,   f4h,  f4l,  1,  HD,  OUTD);

    const float* xin = x;
    int ldx = HD;

    for (int l = 0; l < LL; l++) {
        // bond encoder
        launch_gemm(true,  EE, FEA, HD, edge_attr, FEA,
                    bW1h + (size_t)l*HD*FEA, bW1l + (size_t)l*HD*FEA,
                    bond_b1 + l*HD, tmp, HD);
        launch_gemm(false, EE, HD, HD, tmp, HD,
                    bW2h + (size_t)l*HD*HD, bW2l + (size_t)l*HD*HD,
                    bond_b2 + l*HD, e, HD);

        // aggregate
        init_aggr_k<<<(NN*(HD/4) + 255)/256, 256>>>(xin, ldx, eps, l);
        scatter_k<<<2048, 256>>>(xin, ldx);

        // node MLP
        launch_gemm(true, NN, HD, HD, aggr, HD,
                    mW1h + (size_t)l*HD*HD, mW1l + (size_t)l*HD*HD,
                    mlp_b1 + l*HD, t2, HD);
        launch_gemm(true, NN, HD, HD, t2, HD,
                    mW2h + (size_t)l*HD*HD, mW2l + (size_t)l*HD*HD,
                    mlp_b2 + l*HD, h, HD);

        // batchnorm -> concat slice
        zero_stats_k<<<1, 256>>>();
        bn_reduce_k<<<512, 256>>>();
        bn_apply_k<<<(NN*HD + 255)/256, 256>>>(bn_gamma + l*HD, bn_beta + l*HD, l);

        xin = xc + l*HD;
        ldx = LH;
    }

    pool_k<<<dim3(LH/256, GG), 256>>>();

    launch_gemm(true,  GG, LH, HD,   pooled, LH, f1h, f1l, fc1_b, hh, HD);
    launch_gemm(false, GG, HD, OUTD, hh,     HD, f4h, f4l, fc4_b, out, OUTD);
}

// round 5
// speedup vs baseline: 1.9062x; 1.6139x over previous
#include <cuda_runtime.h>
#include <cuda_bf16.h>
#include <cstdint>
#include <math.h>

#define NN   50000
#define EE   300000
#define FEA  64
#define HD   256
#define GG   256
#define LL   4
#define OUTD 128
#define LH   (LL*HD)   // 1024

// ---------------- scratch (device globals) ---------------------------------
__device__ float g_tmp [(size_t)EE*HD];
__device__ float g_aggr[(size_t)NN*HD];
__device__ float g_t2  [(size_t)NN*HD];
__device__ float g_h   [(size_t)NN*HD];
__device__ float g_xc  [(size_t)NN*LH];
__device__ float g_sum [HD];
__device__ float g_ssq [HD];
__device__ float g_pooled[GG*LH];
__device__ float g_hh  [GG*HD];
__device__ int   g_src [EE];
__device__ int   g_dst [EE];
__device__ int   g_batch[NN];
__device__ int   g_off [GG+1];
// weights: transposed to [N, K/2], bf16 hi/lo packed pairs (low 16 = even k)
__device__ uint32_t g_bW1h[LL*HD*FEA/2], g_bW1l[LL*HD*FEA/2];
__device__ uint32_t g_bW2h[LL*HD*HD/2],  g_bW2l[LL*HD*HD/2];
__device__ uint32_t g_mW1h[LL*HD*HD/2],  g_mW1l[LL*HD*HD/2];
__device__ uint32_t g_mW2h[LL*HD*HD/2],  g_mW2l[LL*HD*HD/2];
__device__ uint32_t g_f1h [HD*LH/2],     g_f1l [HD*LH/2];
__device__ uint32_t g_f4h [OUTD*HD/2],   g_f4l [OUTD*HD/2];

// ---------------- helpers ---------------------------------------------------
__device__ __forceinline__ void mma_bf16(float* d, const uint32_t* a,
                                         uint32_t b0, uint32_t b1) {
    asm volatile(
        "mma.sync.aligned.m16n8k16.row.col.f32.bf16.bf16.f32 "
        "{%0,%1,%2,%3}, {%4,%5,%6,%7}, {%8,%9}, {%0,%1,%2,%3};"
        : "+f"(d[0]), "+f"(d[1]), "+f"(d[2]), "+f"(d[3])
        : "r"(a[0]), "r"(a[1]), "r"(a[2]), "r"(a[3]), "r"(b0), "r"(b1));
}
__device__ __forceinline__ uint32_t pack_bf2(__nv_bfloat162 v) {
    return *reinterpret_cast<uint32_t*>(&v);
}

// SMEM word strides: A [k2 (16 rows)][m], B [n (128 rows)][k2]
#define SAK 136   // 136 % 32 == 8  -> frag banks = 8*qid + grp (all distinct)
#define SBK 20    // 20  % 32 == 20 -> frag banks = 20*grp + qid (all distinct)

// ---------------- 3xBF16 tensor-core GEMM: C = A[M,K] @ B + bias -----------
// B pre-transposed/split as Bh/Bl packed bf16x2 [Ntot][K/2]. K%32==0, Ntot%128==0.
// SCATTER variant: instead of storing C, does aggr[dst[row]] += relu(x[src[row]] + C).
template<bool RELU, bool SCATTER>
__global__ void __launch_bounds__(256, 2)
bf_gemm(int M, int K,
        const float* __restrict__ A, int lda,
        const uint32_t* __restrict__ Bh, const uint32_t* __restrict__ Bl,
        const float* __restrict__ bias,
        float* __restrict__ C, int ldc,
        const int* __restrict__ src, const int* __restrict__ dst,
        const float* __restrict__ xg, int ldx, float* __restrict__ aggr)
{
    __shared__ uint32_t Ahs[16*SAK], Als[16*SAK];
    __shared__ uint32_t Bhs[128*SBK], Bls[128*SBK];

    const int tid  = threadIdx.x;
    const int wid  = tid >> 5;
    const int lane = tid & 31;
    const int warp_m = wid & 1;     // 2 warps over M (64 each)
    const int warp_n = wid >> 1;    // 4 warps over N (32 each)
    const int m0 = blockIdx.y * 128;
    const int n0 = blockIdx.x * 128;

    const int ldrow  = tid >> 1;    // 0..127
    const int ldhalf = tid & 1;
    const bool aok = (m0 + ldrow) < M;
    const int K2 = K >> 1;

    float acc[4][4][4];
    #pragma unroll
    for (int i = 0; i < 4; i++)
        #pragma unroll
        for (int j = 0; j < 4; j++)
            #pragma unroll
            for (int q = 0; q < 4; q++) acc[i][j][q] = 0.f;

    const int grp = lane >> 2;      // 0..7
    const int qid = lane & 3;       // 0..3

    const int nch = K >> 5;         // K-chunks of 32
    for (int c = 0; c < nch; c++) {
        __syncthreads();
        // ---- stage A (fp32 -> bf16 hi/lo, packed pairs) ----
        {
            const float* Ap = A + (size_t)(m0 + ldrow) * lda + c * 32 + ldhalf * 16;
            #pragma unroll
            for (int j = 0; j < 4; j++) {
                float4 av = aok ? *(const float4*)(Ap + j * 4)
                                : make_float4(0.f, 0.f, 0.f, 0.f);
                __nv_bfloat162 h01 = __floats2bfloat162_rn(av.x, av.y);
                __nv_bfloat162 h23 = __floats2bfloat162_rn(av.z, av.w);
                __nv_bfloat162 l01 = __floats2bfloat162_rn(
                    av.x - __low2float(h01), av.y - __high2float(h01));
                __nv_bfloat162 l23 = __floats2bfloat162_rn(
                    av.z - __low2float(h23), av.w - __high2float(h23));
                const int k2 = ldhalf * 8 + 2 * j;
                Ahs[(k2    ) * SAK + ldrow] = pack_bf2(h01);
                Ahs[(k2 + 1) * SAK + ldrow] = pack_bf2(h23);
                Als[(k2    ) * SAK + ldrow] = pack_bf2(l01);
                Als[(k2 + 1) * SAK + ldrow] = pack_bf2(l23);
            }
        }
        // ---- stage B (already packed bf16) ----
        {
            const uint32_t* Bhp = Bh + (size_t)(n0 + ldrow) * K2 + c * 16 + ldhalf * 8;
            const uint32_t* Blp = Bl + (size_t)(n0 + ldrow) * K2 + c * 16 + ldhalf * 8;
            uint4 v0 = *(const uint4*)(Bhp);
            uint4 v1 = *(const uint4*)(Bhp + 4);
            uint4 w0 = *(const uint4*)(Blp);
            uint4 w1 = *(const uint4*)(Blp + 4);
            uint32_t* bh = &Bhs[ldrow * SBK + ldhalf * 8];
            uint32_t* bl = &Bls[ldrow * SBK + ldhalf * 8];
            bh[0]=v0.x; bh[1]=v0.y; bh[2]=v0.z; bh[3]=v0.w;
            bh[4]=v1.x; bh[5]=v1.y; bh[6]=v1.z; bh[7]=v1.w;
            bl[0]=w0.x; bl[1]=w0.y; bl[2]=w0.z; bl[3]=w0.w;
            bl[4]=w1.x; bl[5]=w1.y; bl[6]=w1.z; bl[7]=w1.w;
        }
        __syncthreads();

        #pragma unroll
        for (int s = 0; s < 2; s++) {          // two k16 steps per chunk
            const int k2b = s * 8;
            uint32_t afh[4][4], afl[4][4];
            #pragma unroll
            for (int mf = 0; mf < 4; mf++) {
                const int mr = warp_m * 64 + mf * 16 + grp;
                afh[mf][0] = Ahs[(k2b + qid    ) * SAK + mr    ];
                afh[mf][1] = Ahs[(k2b + qid    ) * SAK + mr + 8];
                afh[mf][2] = Ahs[(k2b + qid + 4) * SAK + mr    ];
                afh[mf][3] = Ahs[(k2b + qid + 4) * SAK + mr + 8];
                afl[mf][0] = Als[(k2b + qid    ) * SAK + mr    ];
                afl[mf][1] = Als[(k2b + qid    ) * SAK + mr + 8];
                afl[mf][2] = Als[(k2b + qid + 4) * SAK + mr    ];
                afl[mf][3] = Als[(k2b + qid + 4) * SAK + mr + 8];
            }
            #pragma unroll
            for (int nf = 0; nf < 4; nf++) {
                const int nn = warp_n * 32 + nf * 8 + grp;
                uint32_t bh0 = Bhs[nn * SBK + k2b + qid];
                uint32_t bh1 = Bhs[nn * SBK + k2b + qid + 4];
                uint32_t bl0 = Bls[nn * SBK + k2b + qid];
                uint32_t bl1 = Bls[nn * SBK + k2b + qid + 4];
                #pragma unroll
                for (int mf = 0; mf < 4; mf++) {
                    mma_bf16(acc[mf][nf], afh[mf], bh0, bh1);  // Ah*Bh
                    mma_bf16(acc[mf][nf], afh[mf], bl0, bl1);  // Ah*Bl
                    mma_bf16(acc[mf][nf], afl[mf], bh0, bh1);  // Al*Bh
                }
            }
        }
    }

    // ---- epilogue ----
    #pragma unroll
    for (int mf = 0; mf < 4; mf++) {
        #pragma unroll
        for (int half = 0; half < 2; half++) {
            const int row = m0 + warp_m * 64 + mf * 16 + grp + half * 8;
            if (row >= M) continue;
            if (SCATTER) {
                const int sn = src[row];
                const int dn = dst[row];
                const float* xr = xg + (size_t)sn * ldx;
                float* ar = aggr + (size_t)dn * HD;
                #pragma unroll
                for (int nf = 0; nf < 4; nf++) {
                    const int col = n0 + warp_n * 32 + nf * 8 + 2 * qid;
                    float2 xv = *(const float2*)(xr + col);
                    float v0 = acc[mf][nf][2*half+0] + bias[col]     + xv.x;
                    float v1 = acc[mf][nf][2*half+1] + bias[col + 1] + xv.y;
                    v0 = fmaxf(v0, 0.f); v1 = fmaxf(v1, 0.f);
                    atomicAdd(ar + col,     v0);
                    atomicAdd(ar + col + 1, v1);
                }
            } else {
                #pragma unroll
                for (int nf = 0; nf < 4; nf++) {
                    const int col = n0 + warp_n * 32 + nf * 8 + 2 * qid;
                    float v0 = acc[mf][nf][2*half+0] + bias[col];
                    float v1 = acc[mf][nf][2*half+1] + bias[col + 1];
                    if (RELU) { v0 = fmaxf(v0, 0.f); v1 = fmaxf(v1, 0.f); }
                    *(float2*)(C + (size_t)row * ldc + col) = make_float2(v0, v1);
                }
            }
        }
    }
}

// ---------------- weight transpose + bf16 hi/lo split + pack ---------------
// in: [Lc, K, N]  ->  hi/lo packed bf16x2: [Lc, N, K/2]
__global__ void split_pack_k(const float* __restrict__ in,
                             uint32_t* __restrict__ hi, uint32_t* __restrict__ lo,
                             int Lc, int K, int N) {
    int i = blockIdx.x * blockDim.x + threadIdx.x;
    const int K2 = K >> 1;
    int tot = Lc * N * K2;
    if (i >= tot) return;
    int l = i / (N * K2);
    int r = i % (N * K2);
    int n = r / K2, k2 = r % K2;
    float v0 = in[((size_t)l * K + 2*k2    ) * N + n];
    float v1 = in[((size_t)l * K + 2*k2 + 1) * N + n];
    __nv_bfloat162 h = __floats2bfloat162_rn(v0, v1);
    __nv_bfloat162 lw = __floats2bfloat162_rn(v0 - __low2float(h),
                                              v1 - __high2float(h));
    size_t o = ((size_t)l * N + n) * K2 + k2;
    hi[o] = pack_bf2(h);
    lo[o] = pack_bf2(lw);
}

// ---------------- index conversion (int64 or int32) ------------------------
__global__ void cvt_kernel(const int* __restrict__ ei_raw,
                           const int* __restrict__ batch_raw) {
    bool is64 = (ei_raw[1] == 0) && (ei_raw[3] == 0) && (ei_raw[5] == 0);
    int idx = blockIdx.x * blockDim.x + threadIdx.x;
    int stride = gridDim.x * blockDim.x;
    for (int i = idx; i < EE; i += stride) {
        g_src[i] = is64 ? ei_raw[2*i]        : ei_raw[i];
        g_dst[i] = is64 ? ei_raw[2*(EE + i)] : ei_raw[EE + i];
    }
    for (int i = idx; i < NN; i += stride)
        g_batch[i] = is64 ? batch_raw[2*i] : batch_raw[i];
}

__global__ void off_kernel() {
    int g = blockIdx.x * blockDim.x + threadIdx.x;
    if (g > GG) return;
    int lo = 0, hi = NN;
    while (lo < hi) {
        int mid = (lo + hi) >> 1;
        if (g_batch[mid] < g) lo = mid + 1; else hi = mid;
    }
    g_off[g] = lo;
}

// ---------------- aggr = (1+eps[l]) * x_in ---------------------------------
__global__ void init_aggr_k(const float* __restrict__ xin, int ldx,
                            const float* __restrict__ eps, int l) {
    float a = 1.0f + eps[l];
    int i = blockIdx.x * blockDim.x + threadIdx.x;
    const int total = NN * (HD / 4);
    if (i < total) {
        int row = i / (HD / 4);
        int c4  = i % (HD / 4);
        float4 v = *reinterpret_cast<const float4*>(xin + (size_t)row * ldx + c4 * 4);
        float4 o = make_float4(a*v.x, a*v.y, a*v.z, a*v.w);
        *reinterpret_cast<float4*>(g_aggr + (size_t)row * HD + c4 * 4) = o;
    }
}

// ---------------- batchnorm -------------------------------------------------
__global__ void zero_stats_k() {
    int t = threadIdx.x;
    if (t < HD) { g_sum[t] = 0.f; g_ssq[t] = 0.f; }
}
__global__ void bn_reduce_k() {
    int col = threadIdx.x;
    float s = 0.f, ss = 0.f;
    for (int r = blockIdx.x; r < NN; r += gridDim.x) {
        float v = g_h[(size_t)r * HD + col];
        s += v; ss += v * v;
    }
    atomicAdd(&g_sum[col], s);
    atomicAdd(&g_ssq[col], ss);
}
__global__ void bn_apply_k(const float* __restrict__ gamma,
                           const float* __restrict__ beta, int l) {
    int i = blockIdx.x * blockDim.x + threadIdx.x;
    if (i >= NN * HD) return;
    int col = i & (HD - 1);
    int row = i >> 8;
    float mu  = g_sum[col] * (1.0f / NN);
    float var = g_ssq[col] * (1.0f / NN) - mu * mu;
    float sc  = gamma[col] * rsqrtf(var + 1e-5f);
    g_xc[(size_t)row * LH + l * HD + col] = (g_h[i] - mu) * sc + beta[col];
}

// ---------------- global mean pool ------------------------------------------
__global__ void pool_k() {
    int g   = blockIdx.y;
    int col = blockIdx.x * blockDim.x + threadIdx.x;
    int s  = g_off[g];
    int e2 = g_off[g + 1];
    float acc = 0.f;
    for (int r = s; r < e2; r++) acc += g_xc[(size_t)r * LH + col];
    float cnt = (float)(e2 - s);
    g_pooled[g * LH + col] = acc / fmaxf(cnt, 1.0f);
}

// ---------------- host-side GEMM launchers ----------------------------------
static void launch_gemm(bool relu, int M, int K, int Ntot,
                        const float* A, int lda,
                        const uint32_t* Bh, const uint32_t* Bl,
                        const float* bias, float* C, int ldc) {
    dim3 grid(Ntot / 128, (M + 127) / 128);
    if (relu)
        bf_gemm<true,false><<<grid, 256>>>(M, K, A, lda, Bh, Bl, bias, C, ldc,
                                           nullptr, nullptr, nullptr, 0, nullptr);
    else
        bf_gemm<false,false><<<grid, 256>>>(M, K, A, lda, Bh, Bl, bias, C, ldc,
                                            nullptr, nullptr, nullptr, 0, nullptr);
}

static void launch_gemm_scatter(int M, int K, int Ntot,
                                const float* A, int lda,
                                const uint32_t* Bh, const uint32_t* Bl,
                                const float* bias,
                                const int* src, const int* dst,
                                const float* xg, int ldx, float* aggr) {
    dim3 grid(Ntot / 128, (M + 127) / 128);
    bf_gemm<false,true><<<grid, 256>>>(M, K, A, lda, Bh, Bl, bias, nullptr, 0,
                                       src, dst, xg, ldx, aggr);
}

// ---------------- entry ------------------------------------------------------
extern "C" void kernel_launch(void* const* d_in, const int* in_sizes, int n_in,
                              void* d_out, int out_size) {
    const float* x         = (const float*)d_in[0];
    const int*   ei_raw    = (const int*)  d_in[1];
    const float* edge_attr = (const float*)d_in[2];
    const int*   batch_raw = (const int*)  d_in[3];
    const float* bond_W1   = (const float*)d_in[4];
    const float* bond_b1   = (const float*)d_in[5];
    const float* bond_W2   = (const float*)d_in[6];
    const float* bond_b2   = (const float*)d_in[7];
    const float* mlp_W1    = (const float*)d_in[8];
    const float* mlp_b1    = (const float*)d_in[9];
    const float* mlp_W2    = (const float*)d_in[10];
    const float* mlp_b2    = (const float*)d_in[11];
    const float* eps       = (const float*)d_in[12];
    const float* bn_gamma  = (const float*)d_in[13];
    const float* bn_beta   = (const float*)d_in[14];
    const float* fc1_W     = (const float*)d_in[15];
    const float* fc1_b     = (const float*)d_in[16];
    const float* fc4_W     = (const float*)d_in[17];
    const float* fc4_b     = (const float*)d_in[18];
    float* out = (float*)d_out;

    float *tmp, *aggr, *t2, *h, *xc, *pooled, *hh;
    int *srcp, *dstp;
    cudaGetSymbolAddress((void**)&tmp,    g_tmp);
    cudaGetSymbolAddress((void**)&aggr,   g_aggr);
    cudaGetSymbolAddress((void**)&t2,     g_t2);
    cudaGetSymbolAddress((void**)&h,      g_h);
    cudaGetSymbolAddress((void**)&xc,     g_xc);
    cudaGetSymbolAddress((void**)&pooled, g_pooled);
    cudaGetSymbolAddress((void**)&hh,     g_hh);
    cudaGetSymbolAddress((void**)&srcp,   g_src);
    cudaGetSymbolAddress((void**)&dstp,   g_dst);
    uint32_t *bW1h,*bW1l,*bW2h,*bW2l,*mW1h,*mW1l,*mW2h,*mW2l,*f1h,*f1l,*f4h,*f4l;
    cudaGetSymbolAddress((void**)&bW1h, g_bW1h); cudaGetSymbolAddress((void**)&bW1l, g_bW1l);
    cudaGetSymbolAddress((void**)&bW2h, g_bW2h); cudaGetSymbolAddress((void**)&bW2l, g_bW2l);
    cudaGetSymbolAddress((void**)&mW1h, g_mW1h); cudaGetSymbolAddress((void**)&mW1l, g_mW1l);
    cudaGetSymbolAddress((void**)&mW2h, g_mW2h); cudaGetSymbolAddress((void**)&mW2l, g_mW2l);
    cudaGetSymbolAddress((void**)&f1h,  g_f1h);  cudaGetSymbolAddress((void**)&f1l,  g_f1l);
    cudaGetSymbolAddress((void**)&f4h,  g_f4h);  cudaGetSymbolAddress((void**)&f4l,  g_f4l);

    cvt_kernel<<<256, 256>>>(ei_raw, batch_raw);
    off_kernel<<<2, 256>>>();

    // transpose + bf16 hi/lo split + pack all weights
    split_pack_k<<<(LL*HD*FEA/2 + 255)/256, 256>>>(bond_W1, bW1h, bW1l, LL, FEA, HD);
    split_pack_k<<<(LL*HD*HD/2  + 255)/256, 256>>>(bond_W2, bW2h, bW2l, LL, HD,  HD);
    split_pack_k<<<(LL*HD*HD/2  + 255)/256, 256>>>(mlp_W1,  mW1h, mW1l, LL, HD,  HD);
    split_pack_k<<<(LL*HD*HD/2  + 255)/256, 256>>>(mlp_W2,  mW2h, mW2l, LL, HD,  HD);
    split_pack_k<<<(HD*LH/2     + 255)/256, 256>>>(fc1_W,   f1h,  f1l,  1,  LH,  HD);
    split_pack_k<<<(OUTD*HD/2   + 255)/256, 256>>>(fc4_W,   f4h,  f4l,  1,  HD,  OUTD);

    const float* xin = x;
    int ldx = HD;

    for (int l = 0; l < LL; l++) {
        // bond encoder layer 1: tmp = relu(edge_attr @ W1 + b1)
        launch_gemm(true, EE, FEA, HD, edge_attr, FEA,
                    bW1h + (size_t)l*HD*FEA/2, bW1l + (size_t)l*HD*FEA/2,
                    bond_b1 + l*HD, tmp, HD);

        // aggr = (1+eps)*x  (must precede fused scatter)
        init_aggr_k<<<(NN*(HD/4) + 255)/256, 256>>>(xin, ldx, eps, l);

        // bond layer 2 fused with message+scatter:
        // aggr[dst] += relu(x[src] + tmp@W2 + b2)
        launch_gemm_scatter(EE, HD, HD, tmp, HD,
                            bW2h + (size_t)l*HD*HD/2, bW2l + (size_t)l*HD*HD/2,
                            bond_b2 + l*HD, srcp, dstp, xin, ldx, aggr);

        // node MLP
        launch_gemm(true, NN, HD, HD, aggr, HD,
                    mW1h + (size_t)l*HD*HD/2, mW1l + (size_t)l*HD*HD/2,
                    mlp_b1 + l*HD, t2, HD);
        launch_gemm(true, NN, HD, HD, t2, HD,
                    mW2h + (size_t)l*HD*HD/2, mW2l + (size_t)l*HD*HD/2,
                    mlp_b2 + l*HD, h, HD);

        // batchnorm -> concat slice
        zero_stats_k<<<1, 256>>>();
        bn_reduce_k<<<512, 256>>>();
        bn_apply_k<<<(NN*HD + 255)/256, 256>>>(bn_gamma + l*HD, bn_beta + l*HD, l);

        xin = xc + l*HD;
        ldx = LH;
    }

    pool_k<<<dim3(LH/256, GG), 256>>>();

    launch_gemm(true,  GG, LH, HD,   pooled, LH, f1h, f1l, fc1_b, hh, HD);
    launch_gemm(false, GG, HD, OUTD, hh,     HD, f4h, f4l, fc4_b, out, OUTD);
}

// round 7
// speedup vs baseline: 2.0850x; 1.0938x over previous
#include <cuda_runtime.h>
#include <cuda_bf16.h>
#include <cstdint>
#include <math.h>

#define NN   50000
#define EE   300000
#define FEA  64
#define HD   256
#define GG   256
#define LL   4
#define OUTD 128
#define LH   (LL*HD)   // 1024

// ---------------- scratch (device globals) ---------------------------------
__device__ float g_tmp [(size_t)EE*HD];
__device__ float g_aggr[(size_t)NN*HD];
__device__ float g_t2  [(size_t)NN*HD];
__device__ float g_h   [(size_t)NN*HD];
__device__ float g_xc  [(size_t)NN*LH];
__device__ float g_sum [HD];
__device__ float g_ssq [HD];
__device__ float g_pooled[GG*LH];
__device__ float g_hh  [GG*HD];
__device__ int   g_src [EE];
__device__ int   g_dst [EE];
__device__ int   g_batch[NN];
__device__ int   g_off [GG+1];
// weights: transposed to [N, K/2], bf16 hi/lo packed pairs (low 16 = even k)
__device__ uint32_t g_bW1h[LL*HD*FEA/2], g_bW1l[LL*HD*FEA/2];
__device__ uint32_t g_bW2h[LL*HD*HD/2],  g_bW2l[LL*HD*HD/2];
__device__ uint32_t g_mW1h[LL*HD*HD/2],  g_mW1l[LL*HD*HD/2];
__device__ uint32_t g_mW2h[LL*HD*HD/2],  g_mW2l[LL*HD*HD/2];
__device__ uint32_t g_f1h [HD*LH/2],     g_f1l [HD*LH/2];
__device__ uint32_t g_f4h [OUTD*HD/2],   g_f4l [OUTD*HD/2];

// ---------------- helpers ---------------------------------------------------
__device__ __forceinline__ void mma_bf16(float* d, const uint32_t* a,
                                         uint32_t b0, uint32_t b1) {
    asm volatile(
        "mma.sync.aligned.m16n8k16.row.col.f32.bf16.bf16.f32 "
        "{%0,%1,%2,%3}, {%4,%5,%6,%7}, {%8,%9}, {%0,%1,%2,%3};"
        : "+f"(d[0]), "+f"(d[1]), "+f"(d[2]), "+f"(d[3])
        : "r"(a[0]), "r"(a[1]), "r"(a[2]), "r"(a[3]), "r"(b0), "r"(b1));
}
__device__ __forceinline__ uint32_t pack_bf2(__nv_bfloat162 v) {
    return *reinterpret_cast<uint32_t*>(&v);
}
__device__ __forceinline__ void cp_async16(uint32_t saddr, const void* gptr) {
    asm volatile("cp.async.ca.shared.global [%0], [%1], 16;"
                 :: "r"(saddr), "l"(gptr));
}
__device__ __forceinline__ void cp_commit() {
    asm volatile("cp.async.commit_group;");
}
template<int N>
__device__ __forceinline__ void cp_wait() {
    asm volatile("cp.async.wait_group %0;" :: "n"(N));
}

// SMEM word strides: A [k2 (16 rows)][m], B [n (128 rows)][k2]
#define SAK 136   // frag banks = 8*qid + grp (all distinct)
#define SBK 20    // frag banks = 20*grp + qid (all distinct)
// word offsets in dynamic smem (double buffered)
#define OFF_AH(b) ((b) * 2176)
#define OFF_AL(b) (4352 + (b) * 2176)
#define OFF_BH(b) (8704 + (b) * 2560)
#define OFF_BL(b) (13824 + (b) * 2560)
#define SMEM_WORDS 18944
#define SMEM_BYTES (SMEM_WORDS * 4)   // 75776

// ---------------- pipelined 3xBF16 GEMM: C = A[M,K] @ B + bias -------------
// B pre-transposed/split as Bh/Bl packed bf16x2 [Ntot][K/2]. K%32==0, Ntot%128==0.
// SCATTER: aggr[dst[row]] += relu(x[src[row]] + C) instead of storing C.
template<bool RELU, bool SCATTER>
__global__ void __launch_bounds__(256, 2)
bf_gemm(int M, int K,
        const float* __restrict__ A, int lda,
        const uint32_t* __restrict__ Bh, const uint32_t* __restrict__ Bl,
        const float* __restrict__ bias,
        float* __restrict__ C, int ldc,
        const int* __restrict__ src, const int* __restrict__ dst,
        const float* __restrict__ xg, int ldx, float* __restrict__ aggr)
{
    extern __shared__ uint32_t sm[];

    const int tid  = threadIdx.x;
    const int wid  = tid >> 5;
    const int lane = tid & 31;
    const int warp_m = wid & 1;     // 2 warps over M (64 each)
    const int warp_n = wid >> 1;    // 4 warps over N (32 each)
    const int m0 = blockIdx.y * 128;
    const int n0 = blockIdx.x * 128;

    const int ldrow  = tid >> 1;    // 0..127
    const int ldhalf = tid & 1;
    const bool aok = (m0 + ldrow) < M;
    const int K2 = K >> 1;
    const int nch = K >> 5;         // K-chunks of 32

    const float*    Ap  = A  + (size_t)(m0 + ldrow) * lda + ldhalf * 16;
    const uint32_t* Bhp = Bh + (size_t)(n0 + ldrow) * K2  + ldhalf * 8;
    const uint32_t* Blp = Bl + (size_t)(n0 + ldrow) * K2  + ldhalf * 8;

    // smem byte addresses for this thread's B staging slots
    const uint32_t sbase = (uint32_t)__cvta_generic_to_shared(sm);
    const uint32_t bslot = (ldrow * SBK + ldhalf * 8) * 4;

    const int grp = lane >> 2;      // 0..7
    const int qid = lane & 3;       // 0..3

    float acc[4][4][4];
    #pragma unroll
    for (int i = 0; i < 4; i++)
        #pragma unroll
        for (int j = 0; j < 4; j++)
            #pragma unroll
            for (int q = 0; q < 4; q++) acc[i][j][q] = 0.f;

    // ---- prologue: B chunk 0 via cp.async, A chunk 0 into regs ----
    {
        uint32_t bh_s = sbase + OFF_BH(0) * 4 + bslot;
        uint32_t bl_s = sbase + OFF_BL(0) * 4 + bslot;
        cp_async16(bh_s,      Bhp);
        cp_async16(bh_s + 16, Bhp + 4);
        cp_async16(bl_s,      Blp);
        cp_async16(bl_s + 16, Blp + 4);
        cp_commit();
    }
    float4 ar[4];
    #pragma unroll
    for (int j = 0; j < 4; j++)
        ar[j] = aok ? *(const float4*)(Ap + j * 4)
                    : make_float4(0.f, 0.f, 0.f, 0.f);

    for (int c = 0; c < nch; c++) {
        const int b = c & 1;

        // Guard: all threads must be done READING the buffers we are about to
        // overwrite (B buffer b^1 was read during iteration c-1's compute).
        __syncthreads();

        // ---- issue B prefetch for chunk c+1 ----
        if (c + 1 < nch) {
            uint32_t bh_s = sbase + OFF_BH(b ^ 1) * 4 + bslot;
            uint32_t bl_s = sbase + OFF_BL(b ^ 1) * 4 + bslot;
            const uint32_t* bhp = Bhp + (c + 1) * 16;
            const uint32_t* blp = Blp + (c + 1) * 16;
            cp_async16(bh_s,      bhp);
            cp_async16(bh_s + 16, bhp + 4);
            cp_async16(bl_s,      blp);
            cp_async16(bl_s + 16, blp + 4);
            cp_commit();
        }

        // ---- STS A chunk c (convert fp32 -> bf16 hi/lo) ----
        {
            uint32_t* AhS = sm + OFF_AH(b);
            uint32_t* AlS = sm + OFF_AL(b);
            #pragma unroll
            for (int j = 0; j < 4; j++) {
                float4 av = ar[j];
                __nv_bfloat162 h01 = __floats2bfloat162_rn(av.x, av.y);
                __nv_bfloat162 h23 = __floats2bfloat162_rn(av.z, av.w);
                __nv_bfloat162 l01 = __floats2bfloat162_rn(
                    av.x - __low2float(h01), av.y - __high2float(h01));
                __nv_bfloat162 l23 = __floats2bfloat162_rn(
                    av.z - __low2float(h23), av.w - __high2float(h23));
                const int k2 = ldhalf * 8 + 2 * j;
                AhS[(k2    ) * SAK + ldrow] = pack_bf2(h01);
                AhS[(k2 + 1) * SAK + ldrow] = pack_bf2(h23);
                AlS[(k2    ) * SAK + ldrow] = pack_bf2(l01);
                AlS[(k2 + 1) * SAK + ldrow] = pack_bf2(l23);
            }
        }

        // ---- LDG A chunk c+1 into regs ----
        if (c + 1 < nch) {
            const float* ap = Ap + (c + 1) * 32;
            #pragma unroll
            for (int j = 0; j < 4; j++)
                ar[j] = aok ? *(const float4*)(ap + j * 4)
                            : make_float4(0.f, 0.f, 0.f, 0.f);
        }

        // ---- wait for B chunk c; barrier; compute ----
        if (c + 1 < nch) cp_wait<1>(); else cp_wait<0>();
        __syncthreads();

        const uint32_t* AhS = sm + OFF_AH(b);
        const uint32_t* AlS = sm + OFF_AL(b);
        const uint32_t* BhS = sm + OFF_BH(b);
        const uint32_t* BlS = sm + OFF_BL(b);

        #pragma unroll
        for (int s = 0; s < 2; s++) {          // two k16 steps per chunk
            const int k2b = s * 8;
            uint32_t bh0[4], bh1[4], bl0[4], bl1[4];
            #pragma unroll
            for (int nf = 0; nf < 4; nf++) {
                const int nn = warp_n * 32 + nf * 8 + grp;
                bh0[nf] = BhS[nn * SBK + k2b + qid];
                bh1[nf] = BhS[nn * SBK + k2b + qid + 4];
                bl0[nf] = BlS[nn * SBK + k2b + qid];
                bl1[nf] = BlS[nn * SBK + k2b + qid + 4];
            }
            #pragma unroll
            for (int mf = 0; mf < 4; mf++) {
                const int mr = warp_m * 64 + mf * 16 + grp;
                uint32_t ah[4], al[4];
                ah[0] = AhS[(k2b + qid    ) * SAK + mr    ];
                ah[1] = AhS[(k2b + qid    ) * SAK + mr + 8];
                ah[2] = AhS[(k2b + qid + 4) * SAK + mr    ];
                ah[3] = AhS[(k2b + qid + 4) * SAK + mr + 8];
                al[0] = AlS[(k2b + qid    ) * SAK + mr    ];
                al[1] = AlS[(k2b + qid    ) * SAK + mr + 8];
                al[2] = AlS[(k2b + qid + 4) * SAK + mr    ];
                al[3] = AlS[(k2b + qid + 4) * SAK + mr + 8];
                #pragma unroll
                for (int nf = 0; nf < 4; nf++) {
                    mma_bf16(acc[mf][nf], ah, bh0[nf], bh1[nf]);  // Ah*Bh
                    mma_bf16(acc[mf][nf], ah, bl0[nf], bl1[nf]);  // Ah*Bl
                    mma_bf16(acc[mf][nf], al, bh0[nf], bh1[nf]);  // Al*Bh
                }
            }
        }
    }

    // ---- epilogue ----
    #pragma unroll
    for (int mf = 0; mf < 4; mf++) {
        #pragma unroll
        for (int half = 0; half < 2; half++) {
            const int row = m0 + warp_m * 64 + mf * 16 + grp + half * 8;
            if (row >= M) continue;
            if (SCATTER) {
                const int sn = src[row];
                const int dn = dst[row];
                const float* xr = xg + (size_t)sn * ldx;
                float* arow = aggr + (size_t)dn * HD;
                #pragma unroll
                for (int nf = 0; nf < 4; nf++) {
                    const int col = n0 + warp_n * 32 + nf * 8 + 2 * qid;
                    float2 xv = *(const float2*)(xr + col);
                    float v0 = acc[mf][nf][2*half+0] + bias[col]     + xv.x;
                    float v1 = acc[mf][nf][2*half+1] + bias[col + 1] + xv.y;
                    v0 = fmaxf(v0, 0.f); v1 = fmaxf(v1, 0.f);
                    atomicAdd(arow + col,     v0);
                    atomicAdd(arow + col + 1, v1);
                }
            } else {
                #pragma unroll
                for (int nf = 0; nf < 4; nf++) {
                    const int col = n0 + warp_n * 32 + nf * 8 + 2 * qid;
                    float v0 = acc[mf][nf][2*half+0] + bias[col];
                    float v1 = acc[mf][nf][2*half+1] + bias[col + 1];
                    if (RELU) { v0 = fmaxf(v0, 0.f); v1 = fmaxf(v1, 0.f); }
                    *(float2*)(C + (size_t)row * ldc + col) = make_float2(v0, v1);
                }
            }
        }
    }
}

// ---------------- weight transpose + bf16 hi/lo split + pack ---------------
// in: [Lc, K, N]  ->  hi/lo packed bf16x2: [Lc, N, K/2]
__global__ void split_pack_k(const float* __restrict__ in,
                             uint32_t* __restrict__ hi, uint32_t* __restrict__ lo,
                             int Lc, int K, int N) {
    int i = blockIdx.x * blockDim.x + threadIdx.x;
    const int K2 = K >> 1;
    int tot = Lc * N * K2;
    if (i >= tot) return;
    int l = i / (N * K2);
    int r = i % (N * K2);
    int n = r / K2, k2 = r % K2;
    float v0 = in[((size_t)l * K + 2*k2    ) * N + n];
    float v1 = in[((size_t)l * K + 2*k2 + 1) * N + n];
    __nv_bfloat162 h = __floats2bfloat162_rn(v0, v1);
    __nv_bfloat162 lw = __floats2bfloat162_rn(v0 - __low2float(h),
                                              v1 - __high2float(h));
    size_t o = ((size_t)l * N + n) * K2 + k2;
    hi[o] = pack_bf2(h);
    lo[o] = pack_bf2(lw);
}

// ---------------- index conversion (int64 or int32) ------------------------
__global__ void cvt_kernel(const int* __restrict__ ei_raw,
                           const int* __restrict__ batch_raw) {
    bool is64 = (ei_raw[1] == 0) && (ei_raw[3] == 0) && (ei_raw[5] == 0);
    int idx = blockIdx.x * blockDim.x + threadIdx.x;
    int stride = gridDim.x * blockDim.x;
    for (int i = idx; i < EE; i += stride) {
        g_src[i] = is64 ? ei_raw[2*i]        : ei_raw[i];
        g_dst[i] = is64 ? ei_raw[2*(EE + i)] : ei_raw[EE + i];
    }
    for (int i = idx; i < NN; i += stride)
        g_batch[i] = is64 ? batch_raw[2*i] : batch_raw[i];
}

__global__ void off_kernel() {
    int g = blockIdx.x * blockDim.x + threadIdx.x;
    if (g > GG) return;
    int lo = 0, hi = NN;
    while (lo < hi) {
        int mid = (lo + hi) >> 1;
        if (g_batch[mid] < g) lo = mid + 1; else hi = mid;
    }
    g_off[g] = lo;
}

// ---------------- aggr = (1+eps[l]) * x_in ---------------------------------
__global__ void init_aggr_k(const float* __restrict__ xin, int ldx,
                            const float* __restrict__ eps, int l) {
    float a = 1.0f + eps[l];
    int i = blockIdx.x * blockDim.x + threadIdx.x;
    const int total = NN * (HD / 4);
    if (i < total) {
        int row = i / (HD / 4);
        int c4  = i % (HD / 4);
        float4 v = *reinterpret_cast<const float4*>(xin + (size_t)row * ldx + c4 * 4);
        float4 o = make_float4(a*v.x, a*v.y, a*v.z, a*v.w);
        *reinterpret_cast<float4*>(g_aggr + (size_t)row * HD + c4 * 4) = o;
    }
}

// ---------------- batchnorm -------------------------------------------------
__global__ void zero_stats_k() {
    int t = threadIdx.x;
    if (t < HD) { g_sum[t] = 0.f; g_ssq[t] = 0.f; }
}
__global__ void bn_reduce_k() {
    int col = threadIdx.x;
    float s = 0.f, ss = 0.f;
    for (int r = blockIdx.x; r < NN; r += gridDim.x) {
        float v = g_h[(size_t)r * HD + col];
        s += v; ss += v * v;
    }
    atomicAdd(&g_sum[col], s);
    atomicAdd(&g_ssq[col], ss);
}
__global__ void bn_apply_k(const float* __restrict__ gamma,
                           const float* __restrict__ beta, int l) {
    int i = blockIdx.x * blockDim.x + threadIdx.x;
    if (i >= NN * HD) return;
    int col = i & (HD - 1);
    int row = i >> 8;
    float mu  = g_sum[col] * (1.0f / NN);
    float var = g_ssq[col] * (1.0f / NN) - mu * mu;
    float sc  = gamma[col] * rsqrtf(var + 1e-5f);
    g_xc[(size_t)row * LH + l * HD + col] = (g_h[i] - mu) * sc + beta[col];
}

// ---------------- global mean pool ------------------------------------------
__global__ void pool_k() {
    int g   = blockIdx.y;
    int col = blockIdx.x * blockDim.x + threadIdx.x;
    int s  = g_off[g];
    int e2 = g_off[g + 1];
    float acc = 0.f;
    for (int r = s; r < e2; r++) acc += g_xc[(size_t)r * LH + col];
    float cnt = (float)(e2 - s);
    g_pooled[g * LH + col] = acc / fmaxf(cnt, 1.0f);
}

// ---------------- host-side GEMM launchers ----------------------------------
static void launch_gemm(bool relu, int M, int K, int Ntot,
                        const float* A, int lda,
                        const uint32_t* Bh, const uint32_t* Bl,
                        const float* bias, float* C, int ldc) {
    dim3 grid(Ntot / 128, (M + 127) / 128);
    if (relu) {
        cudaFuncSetAttribute(bf_gemm<true,false>,
            cudaFuncAttributeMaxDynamicSharedMemorySize, SMEM_BYTES);
        bf_gemm<true,false><<<grid, 256, SMEM_BYTES>>>(M, K, A, lda, Bh, Bl, bias,
            C, ldc, nullptr, nullptr, nullptr, 0, nullptr);
    } else {
        cudaFuncSetAttribute(bf_gemm<false,false>,
            cudaFuncAttributeMaxDynamicSharedMemorySize, SMEM_BYTES);
        bf_gemm<false,false><<<grid, 256, SMEM_BYTES>>>(M, K, A, lda, Bh, Bl, bias,
            C, ldc, nullptr, nullptr, nullptr, 0, nullptr);
    }
}

static void launch_gemm_scatter(int M, int K, int Ntot,
                                const float* A, int lda,
                                const uint32_t* Bh, const uint32_t* Bl,
                                const float* bias,
                                const int* src, const int* dst,
                                const float* xg, int ldx, float* aggr) {
    dim3 grid(Ntot / 128, (M + 127) / 128);
    cudaFuncSetAttribute(bf_gemm<false,true>,
        cudaFuncAttributeMaxDynamicSharedMemorySize, SMEM_BYTES);
    bf_gemm<false,true><<<grid, 256, SMEM_BYTES>>>(M, K, A, lda, Bh, Bl, bias,
        nullptr, 0, src, dst, xg, ldx, aggr);
}

// ---------------- entry ------------------------------------------------------
extern "C" void kernel_launch(void* const* d_in, const int* in_sizes, int n_in,
                              void* d_out, int out_size) {
    const float* x         = (const float*)d_in[0];
    const int*   ei_raw    = (const int*)  d_in[1];
    const float* edge_attr = (const float*)d_in[2];
    const int*   batch_raw = (const int*)  d_in[3];
    const float* bond_W1   = (const float*)d_in[4];
    const float* bond_b1   = (const float*)d_in[5];
    const float* bond_W2   = (const float*)d_in[6];
    const float* bond_b2   = (const float*)d_in[7];
    const float* mlp_W1    = (const float*)d_in[8];
    const float* mlp_b1    = (const float*)d_in[9];
    const float* mlp_W2    = (const float*)d_in[10];
    const float* mlp_b2    = (const float*)d_in[11];
    const float* eps       = (const float*)d_in[12];
    const float* bn_gamma  = (const float*)d_in[13];
    const float* bn_beta   = (const float*)d_in[14];
    const float* fc1_W     = (const float*)d_in[15];
    const float* fc1_b     = (const float*)d_in[16];
    const float* fc4_W     = (const float*)d_in[17];
    const float* fc4_b     = (const float*)d_in[18];
    float* out = (float*)d_out;

    float *tmp, *aggr, *t2, *h, *xc, *pooled, *hh;
    int *srcp, *dstp;
    cudaGetSymbolAddress((void**)&tmp,    g_tmp);
    cudaGetSymbolAddress((void**)&aggr,   g_aggr);
    cudaGetSymbolAddress((void**)&t2,     g_t2);
    cudaGetSymbolAddress((void**)&h,      g_h);
    cudaGetSymbolAddress((void**)&xc,     g_xc);
    cudaGetSymbolAddress((void**)&pooled, g_pooled);
    cudaGetSymbolAddress((void**)&hh,     g_hh);
    cudaGetSymbolAddress((void**)&srcp,   g_src);
    cudaGetSymbolAddress((void**)&dstp,   g_dst);
    uint32_t *bW1h,*bW1l,*bW2h,*bW2l,*mW1h,*mW1l,*mW2h,*mW2l,*f1h,*f1l,*f4h,*f4l;
    cudaGetSymbolAddress((void**)&bW1h, g_bW1h); cudaGetSymbolAddress((void**)&bW1l, g_bW1l);
    cudaGetSymbolAddress((void**)&bW2h, g_bW2h); cudaGetSymbolAddress((void**)&bW2l, g_bW2l);
    cudaGetSymbolAddress((void**)&mW1h, g_mW1h); cudaGetSymbolAddress((void**)&mW1l, g_mW1l);
    cudaGetSymbolAddress((void**)&mW2h, g_mW2h); cudaGetSymbolAddress((void**)&mW2l, g_mW2l);
    cudaGetSymbolAddress((void**)&f1h,  g_f1h);  cudaGetSymbolAddress((void**)&f1l,  g_f1l);
    cudaGetSymbolAddress((void**)&f4h,  g_f4h);  cudaGetSymbolAddress((void**)&f4l,  g_f4l);

    cvt_kernel<<<256, 256>>>(ei_raw, batch_raw);
    off_kernel<<<2, 256>>>();

    // transpose + bf16 hi/lo split + pack all weights
    split_pack_k<<<(LL*HD*FEA/2 + 255)/256, 256>>>(bond_W1, bW1h, bW1l, LL, FEA, HD);
    split_pack_k<<<(LL*HD*HD/2  + 255)/256, 256>>>(bond_W2, bW2h, bW2l, LL, HD,  HD);
    split_pack_k<<<(LL*HD*HD/2  + 255)/256, 256>>>(mlp_W1,  mW1h, mW1l, LL, HD,  HD);
    split_pack_k<<<(LL*HD*HD/2  + 255)/256, 256>>>(mlp_W2,  mW2h, mW2l, LL, HD,  HD);
    split_pack_k<<<(HD*LH/2     + 255)/256, 256>>>(fc1_W,   f1h,  f1l,  1,  LH,  HD);
    split_pack_k<<<(OUTD*HD/2   + 255)/256, 256>>>(fc4_W,   f4h,  f4l,  1,  HD,  OUTD);

    const float* xin = x;
    int ldx = HD;

    for (int l = 0; l < LL; l++) {
        // bond encoder layer 1: tmp = relu(edge_attr @ W1 + b1)
        launch_gemm(true, EE, FEA, HD, edge_attr, FEA,
                    bW1h + (size_t)l*HD*FEA/2, bW1l + (size_t)l*HD*FEA/2,
                    bond_b1 + l*HD, tmp, HD);

        // aggr = (1+eps)*x  (must precede fused scatter)
        init_aggr_k<<<(NN*(HD/4) + 255)/256, 256>>>(xin, ldx, eps, l);

        // bond layer 2 fused with message+scatter:
        // aggr[dst] += relu(x[src] + tmp@W2 + b2)
        launch_gemm_scatter(EE, HD, HD, tmp, HD,
                            bW2h + (size_t)l*HD*HD/2, bW2l + (size_t)l*HD*HD/2,
                            bond_b2 + l*HD, srcp, dstp, xin, ldx, aggr);

        // node MLP
        launch_gemm(true, NN, HD, HD, aggr, HD,
                    mW1h + (size_t)l*HD*HD/2, mW1l + (size_t)l*HD*HD/2,
                    mlp_b1 + l*HD, t2, HD);
        launch_gemm(true, NN, HD, HD, t2, HD,
                    mW2h + (size_t)l*HD*HD/2, mW2l + (size_t)l*HD*HD/2,
                    mlp_b2 + l*HD, h, HD);

        // batchnorm -> concat slice
        zero_stats_k<<<1, 256>>>();
        bn_reduce_k<<<512, 256>>>();
        bn_apply_k<<<(NN*HD + 255)/256, 256>>>(bn_gamma + l*HD, bn_beta + l*HD, l);

        xin = xc + l*HD;
        ldx = LH;
    }

    pool_k<<<dim3(LH/256, GG), 256>>>();

    launch_gemm(true,  GG, LH, HD,   pooled, LH, f1h, f1l, fc1_b, hh, HD);
    launch_gemm(false, GG, HD, OUTD, hh,     HD, f4h, f4l, fc4_b, out, OUTD);
}